// round 15
// baseline (speedup 1.0000x reference)
#include <cuda_runtime.h>
#include <cuda_fp16.h>
#include <cstdint>

// Problem sizes
#define BB   128
#define TT   256
#define CC   384
#define HH   6
#define HSZ  64
#define MTOT (BB*TT)          // 32768
#define NQKV 1152
#define CW   192              // CC/2 half2-words per row

// Scratch: fp16 data stored as half2 packed in unsigned words
__device__ __align__(16) unsigned g_xh[MTOT*CW];        // x fp16
__device__ __align__(16) unsigned g_wqkvh[NQKV*CW];     // B[n][k] fp16, Wq pre-scaled
__device__ __align__(16) unsigned g_wph[CC*CW];         // Wp[n][k] fp16
__device__ __align__(16) unsigned g_qh[BB*HH*TT*32];    // [B][H][T][64] fp16 (pre-scaled)
__device__ __align__(16) unsigned g_kh[BB*HH*TT*32];
__device__ __align__(16) unsigned g_vh[BB*HH*TT*32];
__device__ __align__(16) unsigned g_atth[MTOT*CW];      // [B][T][384] fp16

#define QSCALE 0.1803368801111204f   // 0.125 * log2(e)

__device__ __forceinline__ unsigned packh2(float lo, float hi) {
    unsigned u;
    asm("cvt.rn.f16x2.f32 %0, %1, %2;" : "=r"(u) : "f"(hi), "f"(lo));
    return u;
}

__device__ __forceinline__ float ex2f(float x) {
    float y;
    asm("ex2.approx.f32 %0, %1;" : "=f"(y) : "f"(x));
    return y;
}

__device__ __forceinline__ void cp_async16(unsigned* smem_dst, const unsigned* gsrc) {
    unsigned s = (unsigned)__cvta_generic_to_shared(smem_dst);
    asm volatile("cp.async.cg.shared.global [%0], [%1], 16;\n" :: "r"(s), "l"(gsrc));
}
#define CP_COMMIT() asm volatile("cp.async.commit_group;\n" ::: "memory")
#define CP_WAIT(N)  asm volatile("cp.async.wait_group %0;\n" :: "n"(N) : "memory")

// fp16 mma m16n8k16, fp32 accumulate
__device__ __forceinline__ void mma16(float& c0, float& c1, float& c2, float& c3,
                                      unsigned a0, unsigned a1, unsigned a2, unsigned a3,
                                      unsigned b0, unsigned b1) {
    asm volatile(
        "mma.sync.aligned.m16n8k16.row.col.f32.f16.f16.f32 "
        "{%0,%1,%2,%3}, {%4,%5,%6,%7}, {%8,%9}, {%0,%1,%2,%3};\n"
        : "+f"(c0), "+f"(c1), "+f"(c2), "+f"(c3)
        : "r"(a0), "r"(a1), "r"(a2), "r"(a3), "r"(b0), "r"(b1));
}

__device__ __forceinline__ void ldsm_x4(unsigned& r0, unsigned& r1, unsigned& r2, unsigned& r3,
                                        unsigned addr) {
    asm volatile("ldmatrix.sync.aligned.m8n8.x4.shared.b16 {%0,%1,%2,%3}, [%4];"
                 : "=r"(r0), "=r"(r1), "=r"(r2), "=r"(r3) : "r"(addr));
}

// bit-reverse-3 XOR swizzle on word index (16B granularity, bits 2-4)
__device__ __forceinline__ int swz(int r) {
    return ((r & 1) << 4) | ((r & 2) << 2) | (r & 4);
}

// ---------------------------------------------------------------------------
// Merged prep kernel
// ---------------------------------------------------------------------------
#define NCONV (MTOT * CC / (256 * 8))      // 6144
#define NPACK ((NQKV * CW + 255) / 256)    // 864

__global__ void __launch_bounds__(256) prep_kernel(
    const float* __restrict__ x,
    const float* __restrict__ Wq, const float* __restrict__ Wk,
    const float* __restrict__ Wv, const float* __restrict__ Wp)
{
    if (blockIdx.x < NCONV) {
        int i = (blockIdx.x * 256 + threadIdx.x) * 8;
        float4 v0 = *(const float4*)(x + i);
        float4 v1 = *(const float4*)(x + i + 4);
        uint4 o;
        o.x = packh2(v0.x, v0.y);
        o.y = packh2(v0.z, v0.w);
        o.z = packh2(v1.x, v1.y);
        o.w = packh2(v1.z, v1.w);
        *(uint4*)(g_xh + i / 2) = o;
        return;
    }
    int wi = (blockIdx.x - NCONV) * 256 + threadIdx.x;   // word index
    if (wi < NQKV * CW) {
        int n = wi / CW, kw = wi - (wi / CW) * CW;
        int which = n / CC;
        int rem = n - which * CC;
        int h = rem >> 6, d = rem & 63;
        const float* W = (which == 0) ? Wq : ((which == 1) ? Wk : Wv);
        float v0 = W[h * (CC * HSZ) + (2 * kw) * HSZ + d];
        float v1 = W[h * (CC * HSZ) + (2 * kw + 1) * HSZ + d];
        if (which == 0) { v0 *= QSCALE; v1 *= QSCALE; }
        g_wqkvh[wi] = packh2(v0, v1);
    }
    if (wi < CC * CW) {
        int n = wi / CW, kw = wi - (wi / CW) * CW;
        g_wph[wi] = packh2(Wp[n * CC + 2 * kw], Wp[n * CC + 2 * kw + 1]);
    }
}

// ---------------------------------------------------------------------------
// fp16 GEMM: CTA 64x64, 128 threads (4 warps of 32x32), BK=64 halves.
// 2-stage cp.async, one barrier per kt, 6 CTAs/SM (24 warps, +50% occupancy).
// SMEM: 2 x (64+64)x36 words = 36864 B per CTA.
// ---------------------------------------------------------------------------
#define GSTR 36
#define AW3 (64*GSTR)     // 2304 words per A stage
#define BW3 (64*GSTR)     // 2304 words per B stage
#define GEMM_SMEM ((2*AW3 + 2*BW3) * 4)   // 36864 B

__device__ __forceinline__ void gemm_prefetch(unsigned* smA, unsigned* smB,
                                              const unsigned* gA, const unsigned* gB,
                                              int tid) {
    #pragma unroll
    for (int it = 0; it < 4; ++it) {
        int idx = tid + it * 128;       // 0..511: A 64 rows x 8 chunks
        int row = idx >> 3, ch = idx & 7;
        cp_async16(smA + row * GSTR + ch * 4, gA + (size_t)row * CW + ch * 4);
    }
    #pragma unroll
    for (int it = 0; it < 4; ++it) {
        int idx = tid + it * 128;       // 0..511: B 64 rows x 8 chunks
        int row = idx >> 3, ch = idx & 7;
        cp_async16(smB + row * GSTR + ch * 4, gB + (size_t)row * CW + ch * 4);
    }
}

// One compute step (32 mma) using ldmatrix fragment loads.
__device__ __forceinline__ void gemm_compute(unsigned aAddr, unsigned bAddr,
                                             float acc[2][4][4]) {
    #pragma unroll
    for (int ks = 0; ks < 4; ++ks) {
        unsigned af[2][4];
        unsigned bf[4][2];
        #pragma unroll
        for (int im = 0; im < 2; im++)
            ldsm_x4(af[im][0], af[im][1], af[im][2], af[im][3],
                    aAddr + im * (16 * GSTR * 4) + ks * 32);
        #pragma unroll
        for (int jnp = 0; jnp < 2; jnp++)
            ldsm_x4(bf[2 * jnp][0], bf[2 * jnp][1], bf[2 * jnp + 1][0], bf[2 * jnp + 1][1],
                    bAddr + jnp * (16 * GSTR * 4) + ks * 32);
        #pragma unroll
        for (int im = 0; im < 2; im++)
            #pragma unroll
            for (int jn = 0; jn < 4; jn++)
                mma16(acc[im][jn][0], acc[im][jn][1], acc[im][jn][2], acc[im][jn][3],
                      af[im][0], af[im][1], af[im][2], af[im][3],
                      bf[jn][0], bf[jn][1]);
    }
}

__global__ void __launch_bounds__(128, 6) qkv_gemm_kernel()
{
    extern __shared__ unsigned sm[];
    const unsigned smb32 = (unsigned)__cvta_generic_to_shared(sm);
    const int tid  = threadIdx.x;
    const int wid  = tid >> 5;
    const int lane = tid & 31;
    const int g    = lane >> 2;
    const int qd   = lane & 3;

    const int mb = blockIdx.y * 64;
    const int nb = blockIdx.x * 64;
    const int wm = (wid >> 1) * 32;
    const int wn = (wid & 1) * 32;

    // ldmatrix per-thread address offsets (bytes)
    const unsigned aoff = ((wm + (lane & 15)) * GSTR + (lane >> 4) * 4) * 4;
    const unsigned boff = ((wn + ((lane >> 4) << 3) + (lane & 7)) * GSTR + (((lane >> 3) & 1) << 2)) * 4;

    const unsigned* gA = g_xh + (size_t)mb * CW;
    const unsigned* gB = g_wqkvh + (size_t)nb * CW;

    float acc[2][4][4];
    #pragma unroll
    for (int i = 0; i < 2; i++)
        #pragma unroll
        for (int j = 0; j < 4; j++)
            #pragma unroll
            for (int r = 0; r < 4; r++) acc[i][j][r] = 0.f;

    gemm_prefetch(sm, sm + 2 * AW3, gA, gB, tid);
    CP_COMMIT();

    for (int kt = 0; kt < 6; ++kt) {
        CP_WAIT(0);
        __syncthreads();
        if (kt + 1 < 6) {
            int s = (kt + 1) & 1;
            gemm_prefetch(sm + s * AW3, sm + 2 * AW3 + s * BW3,
                          gA + (kt + 1) * 32, gB + (kt + 1) * 32, tid);
            CP_COMMIT();
        }
        int s = kt & 1;
        unsigned aAddr = smb32 + s * (AW3 * 4) + aoff;
        unsigned bAddr = smb32 + (2 * AW3 + s * BW3) * 4 + boff;
        gemm_compute(aAddr, bAddr, acc);
    }

    // Epilogue: pack fp16 and scatter into q/k/v [B][H][T][64]
    #pragma unroll
    for (int im = 0; im < 2; im++) {
        #pragma unroll
        for (int jn = 0; jn < 4; jn++) {
            int mg = mb + wm + 16 * im + g;
            int ng = nb + wn + 8 * jn + 2 * qd;
            int which = ng / CC;
            int rem   = ng - which * CC;
            int hh    = rem >> 6;
            int dw    = (rem & 63) >> 1;
            unsigned* buf = (which == 0) ? g_qh : ((which == 1) ? g_kh : g_vh);
            int b0i = mg >> 8, t0i = mg & 255;
            buf[((b0i * HH + hh) * TT + t0i) * 32 + dw] = packh2(acc[im][jn][0], acc[im][jn][1]);
            int mg2 = mg + 8;
            int b1i = mg2 >> 8, t1i = mg2 & 255;
            buf[((b1i * HH + hh) * TT + t1i) * 32 + dw] = packh2(acc[im][jn][2], acc[im][jn][3]);
        }
    }
}

__global__ void __launch_bounds__(128, 6) proj_gemm_kernel(
    const float* __restrict__ bp,
    float* __restrict__ out)
{
    extern __shared__ unsigned sm[];
    const unsigned smb32 = (unsigned)__cvta_generic_to_shared(sm);
    const int tid  = threadIdx.x;
    const int wid  = tid >> 5;
    const int lane = tid & 31;
    const int g    = lane >> 2;
    const int qd   = lane & 3;

    const int mb = blockIdx.y * 64;
    const int nb = blockIdx.x * 64;
    const int wm = (wid >> 1) * 32;
    const int wn = (wid & 1) * 32;

    const unsigned aoff = ((wm + (lane & 15)) * GSTR + (lane >> 4) * 4) * 4;
    const unsigned boff = ((wn + ((lane >> 4) << 3) + (lane & 7)) * GSTR + (((lane >> 3) & 1) << 2)) * 4;

    const unsigned* gA = g_atth + (size_t)mb * CW;
    const unsigned* gB = g_wph + (size_t)nb * CW;

    float acc[2][4][4];
    #pragma unroll
    for (int i = 0; i < 2; i++)
        #pragma unroll
        for (int j = 0; j < 4; j++)
            #pragma unroll
            for (int r = 0; r < 4; r++) acc[i][j][r] = 0.f;

    gemm_prefetch(sm, sm + 2 * AW3, gA, gB, tid);
    CP_COMMIT();

    for (int kt = 0; kt < 6; ++kt) {
        CP_WAIT(0);
        __syncthreads();
        if (kt + 1 < 6) {
            int s = (kt + 1) & 1;
            gemm_prefetch(sm + s * AW3, sm + 2 * AW3 + s * BW3,
                          gA + (kt + 1) * 32, gB + (kt + 1) * 32, tid);
            CP_COMMIT();
        }
        int s = kt & 1;
        unsigned aAddr = smb32 + s * (AW3 * 4) + aoff;
        unsigned bAddr = smb32 + (2 * AW3 + s * BW3) * 4 + boff;
        gemm_compute(aAddr, bAddr, acc);
    }

    #pragma unroll
    for (int im = 0; im < 2; im++) {
        #pragma unroll
        for (int jn = 0; jn < 4; jn++) {
            int mg = mb + wm + 16 * im + g;
            int ng = nb + wn + 8 * jn + 2 * qd;
            float b0v = bp[ng], b1v = bp[ng + 1];
            float2 v01 = make_float2(acc[im][jn][0] + b0v, acc[im][jn][1] + b1v);
            *(float2*)(out + (size_t)mg * CC + ng) = v01;
            float2 v23 = make_float2(acc[im][jn][2] + b0v, acc[im][jn][3] + b1v);
            *(float2*)(out + (size_t)(mg + 8) * CC + ng) = v23;
        }
    }
}

// ---------------------------------------------------------------------------
// Attention (R13 winner): 4 CTAs per (b,h); CTA q owns rows 64q..64q+63.
// 4 warps x 16 rows, 128 threads, 4 CTAs/SM.
// ---------------------------------------------------------------------------
#define ATQ_W 2048                // Q: 64 rows x 32 words
#define AST_W 4096                // one stage: K 2048 + V 2048 words
#define ATTN_SMEM ((ATQ_W + 2*AST_W) * 4)   // 40960 bytes

__global__ void __launch_bounds__(128, 4) attn_kernel()
{
    extern __shared__ unsigned smem[];
    unsigned* Qs = smem;                     // [64][32] swizzled

    const int bh = blockIdx.x;
    const int q  = 3 - blockIdx.y;           // heavy quarters (q=3) first
    const int b  = bh / HH;
    const int h  = bh - b * HH;

    const int tid  = threadIdx.x;
    const int w    = tid >> 5;               // 0..3
    const int lane = tid & 31;
    const int g    = lane >> 2;
    const int qd   = lane & 3;

    const unsigned* qsrc = g_qh + (size_t)bh * (TT * 32) + q * 64 * 32;
    const unsigned* ksrc = g_kh + (size_t)bh * (TT * 32);
    const unsigned* vsrc = g_vh + (size_t)bh * (TT * 32);

    const unsigned smb32 = (unsigned)__cvta_generic_to_shared(smem);

    // Stage Q (64 rows x 8 chunks = 512) + KV block 0
    #pragma unroll
    for (int i = 0; i < 4; i++) {
        int lin = tid + 128 * i;             // 0..511
        int r = lin >> 3, ch = lin & 7;
        cp_async16(Qs + r * 32 + ((ch * 4) ^ swz(r & 7)), qsrc + r * 32 + ch * 4);
    }
    {
        unsigned* st = smem + ATQ_W;         // stage 0
        #pragma unroll
        for (int i = 0; i < 4; i++) {
            int lin = tid + 128 * i;         // 0..511
            int r = lin >> 3, ch = lin & 7;
            int phys = r * 32 + ((ch * 4) ^ swz(r & 7));
            cp_async16(st + phys,        ksrc + r * 32 + ch * 4);
            cp_async16(st + 2048 + phys, vsrc + r * 32 + ch * 4);
        }
    }
    CP_COMMIT();

    const int wminrow = 64 * q + 16 * w;

    float o[8][4];
    #pragma unroll
    for (int j = 0; j < 8; j++)
        #pragma unroll
        for (int r = 0; r < 4; r++) o[j][r] = 0.f;
    float row_max[2] = {-1e30f, -1e30f};
    float row_sum[2] = {0.f, 0.f};

    const int r0 = 16 * w + g;               // local Q row
    const int sg = swz(g);

    const int lmat = lane >> 3;              // 0..3
    const int lr8  = lane & 7;
    const int vrow_off = ((lmat & 1) << 3) + lr8;    // + 16*ks
    const int vswz = swz(lr8);

    for (int jb = 0; jb <= q; ++jb) {
        CP_WAIT(0);
        __syncthreads();
        if (jb < q) {
            unsigned* st = smem + ATQ_W + ((jb + 1) & 1) * AST_W;
            const unsigned* kg = ksrc + (jb + 1) * 64 * 32;
            const unsigned* vg = vsrc + (jb + 1) * 64 * 32;
            #pragma unroll
            for (int i = 0; i < 4; i++) {
                int lin = tid + 128 * i;
                int r = lin >> 3, ch = lin & 7;
                int phys = r * 32 + ((ch * 4) ^ swz(r & 7));
                cp_async16(st + phys,        kg + r * 32 + ch * 4);
                cp_async16(st + 2048 + phys, vg + r * 32 + ch * 4);
            }
            CP_COMMIT();
        }

        const unsigned* K = smem + ATQ_W + (jb & 1) * AST_W;
        const unsigned vb32 = smb32 + (ATQ_W + (jb & 1) * AST_W + 2048) * 4;

        // ---- S = Q K^T  (4 ksteps of k16) ----
        float s[8][4];
        #pragma unroll
        for (int j = 0; j < 8; j++)
            #pragma unroll
            for (int r = 0; r < 4; r++) s[j][r] = 0.f;

        #pragma unroll
        for (int ks = 0; ks < 4; ++ks) {
            const int cs = (8 * ks + qd) ^ sg;
            unsigned a0 = Qs[r0 * 32 + cs];
            unsigned a1 = Qs[(r0 + 8) * 32 + cs];
            unsigned a2 = Qs[r0 * 32 + (cs ^ 4)];
            unsigned a3 = Qs[(r0 + 8) * 32 + (cs ^ 4)];
            #pragma unroll
            for (int jn = 0; jn < 8; jn++) {
                unsigned b0 = K[(8 * jn + g) * 32 + cs];
                unsigned b1 = K[(8 * jn + g) * 32 + (cs ^ 4)];
                mma16(s[jn][0], s[jn][1], s[jn][2], s[jn][3],
                      a0, a1, a2, a3, b0, b1);
            }
        }

        // ---- causal mask (only the diagonal block jb == q) ----
        if (jb == q) {
            #pragma unroll
            for (int hf = 0; hf < 2; hf++) {
                int trow = wminrow + 8 * hf + g;
                #pragma unroll
                for (int jn = 0; jn < 8; jn++) {
                    #pragma unroll
                    for (int e = 0; e < 2; e++) {
                        int col = jb * 64 + 8 * jn + 2 * qd + e;
                        if (col > trow) s[jn][2 * hf + e] = -1e30f;
                    }
                }
            }
        }

        // ---- online softmax (base-2 domain) ----
        #pragma unroll
        for (int hf = 0; hf < 2; hf++) {
            float rmax = -1e30f;
            #pragma unroll
            for (int jn = 0; jn < 8; jn++) {
                rmax = fmaxf(rmax, fmaxf(s[jn][2 * hf], s[jn][2 * hf + 1]));
            }
            rmax = fmaxf(rmax, __shfl_xor_sync(0xffffffffu, rmax, 1));
            rmax = fmaxf(rmax, __shfl_xor_sync(0xffffffffu, rmax, 2));
            float mnew = fmaxf(row_max[hf], rmax);
            float corr = ex2f(row_max[hf] - mnew);
            row_max[hf] = mnew;
            float psum = 0.f;
            #pragma unroll
            for (int jn = 0; jn < 8; jn++) {
                #pragma unroll
                for (int e = 0; e < 2; e++) {
                    float p = ex2f(s[jn][2 * hf + e] - mnew);
                    s[jn][2 * hf + e] = p;
                    psum += p;
                }
            }
            psum += __shfl_xor_sync(0xffffffffu, psum, 1);
            psum += __shfl_xor_sync(0xffffffffu, psum, 2);
            row_sum[hf] = row_sum[hf] * corr + psum;
            #pragma unroll
            for (int jn = 0; jn < 8; jn++) {
                o[jn][2 * hf + 0] *= corr;
                o[jn][2 * hf + 1] *= corr;
            }
        }

        // ---- O += P V  (P fragment = repacked accumulator, no shuffles) ----
        #pragma unroll
        for (int ks = 0; ks < 4; ++ks) {
            unsigned pa0 = packh2(s[2 * ks][0],     s[2 * ks][1]);
            unsigned pa1 = packh2(s[2 * ks][2],     s[2 * ks][3]);
            unsigned pa2 = packh2(s[2 * ks + 1][0], s[2 * ks + 1][1]);
            unsigned pa3 = packh2(s[2 * ks + 1][2], s[2 * ks + 1][3]);

            unsigned vb[4][4];
            #pragma unroll
            for (int jnp = 0; jnp < 4; jnp++) {
                int vrow = 16 * ks + vrow_off;
                int wc = (4 * (2 * jnp + (lmat >> 1))) ^ vswz;
                unsigned addr = vb32 + (vrow * 32 + wc) * 4;
                asm volatile(
                    "ldmatrix.sync.aligned.m8n8.x4.trans.shared.b16 {%0,%1,%2,%3}, [%4];"
                    : "=r"(vb[jnp][0]), "=r"(vb[jnp][1]), "=r"(vb[jnp][2]), "=r"(vb[jnp][3])
                    : "r"(addr));
            }
            #pragma unroll
            for (int jn = 0; jn < 8; jn++) {
                unsigned b0 = vb[jn >> 1][(jn & 1) * 2];
                unsigned b1 = vb[jn >> 1][(jn & 1) * 2 + 1];
                mma16(o[jn][0], o[jn][1], o[jn][2], o[jn][3],
                      pa0, pa1, pa2, pa3, b0, b1);
            }
        }
    }

    // ---- normalize + store fp16 to g_atth [B][T][384] ----
    float inv0 = 1.0f / row_sum[0];
    float inv1 = 1.0f / row_sum[1];
    int trow = 64 * q + 16 * w + g;
    #pragma unroll
    for (int jn = 0; jn < 8; jn++) {
        int wdd = h * 32 + 4 * jn + qd;
        g_atth[(size_t)(b * TT + trow) * CW + wdd]       = packh2(o[jn][0] * inv0, o[jn][1] * inv0);
        g_atth[(size_t)(b * TT + trow + 8) * CW + wdd]   = packh2(o[jn][2] * inv1, o[jn][3] * inv1);
    }
}

// ---------------------------------------------------------------------------
extern "C" void kernel_launch(void* const* d_in, const int* in_sizes, int n_in,
                              void* d_out, int out_size)
{
    const float* x  = (const float*)d_in[0];
    const float* Wq = (const float*)d_in[1];
    const float* Wk = (const float*)d_in[2];
    const float* Wv = (const float*)d_in[3];
    const float* Wp = (const float*)d_in[4];
    const float* bp = (const float*)d_in[5];
    float* out = (float*)d_out;

    static bool attr_set = false;
    if (!attr_set) {
        cudaFuncSetAttribute(qkv_gemm_kernel,  cudaFuncAttributeMaxDynamicSharedMemorySize, GEMM_SMEM);
        cudaFuncSetAttribute(proj_gemm_kernel, cudaFuncAttributeMaxDynamicSharedMemorySize, GEMM_SMEM);
        cudaFuncSetAttribute(attn_kernel,      cudaFuncAttributeMaxDynamicSharedMemorySize, ATTN_SMEM);
        attr_set = true;
    }

    prep_kernel<<<NCONV + NPACK, 256>>>(x, Wq, Wk, Wv, Wp);
    qkv_gemm_kernel<<<dim3(18, 512), 128, GEMM_SMEM>>>();
    attn_kernel<<<dim3(BB * HH, 4), 128, ATTN_SMEM>>>();
    proj_gemm_kernel<<<dim3(6, 512), 128, GEMM_SMEM>>>(bp, out);
}

// round 16
// speedup vs baseline: 1.0562x; 1.0562x over previous
#include <cuda_runtime.h>
#include <cuda_fp16.h>
#include <cstdint>

// Problem sizes
#define BB   128
#define TT   256
#define CC   384
#define HH   6
#define HSZ  64
#define MTOT (BB*TT)          // 32768
#define NQKV 1152
#define CW   192              // CC/2 half2-words per row

// Scratch: fp16 data stored as half2 packed in unsigned words
__device__ __align__(16) unsigned g_xh[MTOT*CW];        // x fp16
__device__ __align__(16) unsigned g_wqkvh[NQKV*CW];     // B[n][k] fp16, Wq pre-scaled
__device__ __align__(16) unsigned g_wph[CC*CW];         // Wp[n][k] fp16
__device__ __align__(16) unsigned g_qh[BB*HH*TT*32];    // [B][H][T][64] fp16 (pre-scaled)
__device__ __align__(16) unsigned g_kh[BB*HH*TT*32];
__device__ __align__(16) unsigned g_vh[BB*HH*TT*32];
__device__ __align__(16) unsigned g_atth[MTOT*CW];      // [B][T][384] fp16

#define QSCALE 0.1803368801111204f   // 0.125 * log2(e)

__device__ __forceinline__ unsigned packh2(float lo, float hi) {
    unsigned u;
    asm("cvt.rn.f16x2.f32 %0, %1, %2;" : "=r"(u) : "f"(hi), "f"(lo));
    return u;
}

__device__ __forceinline__ float ex2f(float x) {
    float y;
    asm("ex2.approx.f32 %0, %1;" : "=f"(y) : "f"(x));
    return y;
}

__device__ __forceinline__ unsigned ex2h2(unsigned a) {
    unsigned d;
    asm("ex2.approx.f16x2 %0, %1;" : "=r"(d) : "r"(a));
    return d;
}

__device__ __forceinline__ float2 h22f2(unsigned a) {
    float lo, hi;
    asm("{\n\t.reg .f16 l, h;\n\tmov.b32 {l, h}, %2;\n\t"
        "cvt.f32.f16 %0, l;\n\tcvt.f32.f16 %1, h;\n\t}"
        : "=f"(lo), "=f"(hi) : "r"(a));
    return make_float2(lo, hi);
}

__device__ __forceinline__ void cp_async16(unsigned* smem_dst, const unsigned* gsrc) {
    unsigned s = (unsigned)__cvta_generic_to_shared(smem_dst);
    asm volatile("cp.async.cg.shared.global [%0], [%1], 16;\n" :: "r"(s), "l"(gsrc));
}
#define CP_COMMIT() asm volatile("cp.async.commit_group;\n" ::: "memory")
#define CP_WAIT(N)  asm volatile("cp.async.wait_group %0;\n" :: "n"(N) : "memory")

// fp16 mma m16n8k16, fp32 accumulate
__device__ __forceinline__ void mma16(float& c0, float& c1, float& c2, float& c3,
                                      unsigned a0, unsigned a1, unsigned a2, unsigned a3,
                                      unsigned b0, unsigned b1) {
    asm volatile(
        "mma.sync.aligned.m16n8k16.row.col.f32.f16.f16.f32 "
        "{%0,%1,%2,%3}, {%4,%5,%6,%7}, {%8,%9}, {%0,%1,%2,%3};\n"
        : "+f"(c0), "+f"(c1), "+f"(c2), "+f"(c3)
        : "r"(a0), "r"(a1), "r"(a2), "r"(a3), "r"(b0), "r"(b1));
}

__device__ __forceinline__ void ldsm_x4(unsigned& r0, unsigned& r1, unsigned& r2, unsigned& r3,
                                        unsigned addr) {
    asm volatile("ldmatrix.sync.aligned.m8n8.x4.shared.b16 {%0,%1,%2,%3}, [%4];"
                 : "=r"(r0), "=r"(r1), "=r"(r2), "=r"(r3) : "r"(addr));
}

// bit-reverse-3 XOR swizzle on word index (16B granularity, bits 2-4)
__device__ __forceinline__ int swz(int r) {
    return ((r & 1) << 4) | ((r & 2) << 2) | (r & 4);
}

// ---------------------------------------------------------------------------
// Merged prep kernel
// ---------------------------------------------------------------------------
#define NCONV (MTOT * CC / (256 * 8))      // 6144
#define NPACK ((NQKV * CW + 255) / 256)    // 864

__global__ void __launch_bounds__(256) prep_kernel(
    const float* __restrict__ x,
    const float* __restrict__ Wq, const float* __restrict__ Wk,
    const float* __restrict__ Wv, const float* __restrict__ Wp)
{
    if (blockIdx.x < NCONV) {
        int i = (blockIdx.x * 256 + threadIdx.x) * 8;
        float4 v0 = *(const float4*)(x + i);
        float4 v1 = *(const float4*)(x + i + 4);
        uint4 o;
        o.x = packh2(v0.x, v0.y);
        o.y = packh2(v0.z, v0.w);
        o.z = packh2(v1.x, v1.y);
        o.w = packh2(v1.z, v1.w);
        *(uint4*)(g_xh + i / 2) = o;
        return;
    }
    int wi = (blockIdx.x - NCONV) * 256 + threadIdx.x;   // word index
    if (wi < NQKV * CW) {
        int n = wi / CW, kw = wi - (wi / CW) * CW;
        int which = n / CC;
        int rem = n - which * CC;
        int h = rem >> 6, d = rem & 63;
        const float* W = (which == 0) ? Wq : ((which == 1) ? Wk : Wv);
        float v0 = W[h * (CC * HSZ) + (2 * kw) * HSZ + d];
        float v1 = W[h * (CC * HSZ) + (2 * kw + 1) * HSZ + d];
        if (which == 0) { v0 *= QSCALE; v1 *= QSCALE; }
        g_wqkvh[wi] = packh2(v0, v1);
    }
    if (wi < CC * CW) {
        int n = wi / CW, kw = wi - (wi / CW) * CW;
        g_wph[wi] = packh2(Wp[n * CC + 2 * kw], Wp[n * CC + 2 * kw + 1]);
    }
}

// ---------------------------------------------------------------------------
// fp16 GEMM (R13 winner): CTA 128x64, 128 threads (4 warps of 64x32),
// BK=64 halves, 2-stage cp.async, one barrier per kt, 4 CTAs/SM.
// ---------------------------------------------------------------------------
#define GSTR 36
#define AW2 (128*GSTR)    // 4608 words per A stage
#define BW2 (64*GSTR)     // 2304 words per B stage
#define GEMM_SMEM ((2*AW2 + 2*BW2) * 4)   // 55296 B

__device__ __forceinline__ void gemm_prefetch(unsigned* smA, unsigned* smB,
                                              const unsigned* gA, const unsigned* gB,
                                              int tid) {
    #pragma unroll
    for (int it = 0; it < 8; ++it) {
        int idx = tid + it * 128;       // 0..1023: A 128 rows x 8 chunks
        int row = idx >> 3, ch = idx & 7;
        cp_async16(smA + row * GSTR + ch * 4, gA + (size_t)row * CW + ch * 4);
    }
    #pragma unroll
    for (int it = 0; it < 4; ++it) {
        int idx = tid + it * 128;       // 0..511: B 64 rows x 8 chunks
        int row = idx >> 3, ch = idx & 7;
        cp_async16(smB + row * GSTR + ch * 4, gB + (size_t)row * CW + ch * 4);
    }
}

__device__ __forceinline__ void gemm_compute(unsigned aAddr, unsigned bAddr,
                                             float acc[4][4][4]) {
    #pragma unroll
    for (int ks = 0; ks < 4; ++ks) {
        unsigned af[4][4];
        unsigned bf[4][2];
        #pragma unroll
        for (int im = 0; im < 4; im++)
            ldsm_x4(af[im][0], af[im][1], af[im][2], af[im][3],
                    aAddr + im * (16 * GSTR * 4) + ks * 32);
        #pragma unroll
        for (int jnp = 0; jnp < 2; jnp++)
            ldsm_x4(bf[2 * jnp][0], bf[2 * jnp][1], bf[2 * jnp + 1][0], bf[2 * jnp + 1][1],
                    bAddr + jnp * (16 * GSTR * 4) + ks * 32);
        #pragma unroll
        for (int im = 0; im < 4; im++)
            #pragma unroll
            for (int jn = 0; jn < 4; jn++)
                mma16(acc[im][jn][0], acc[im][jn][1], acc[im][jn][2], acc[im][jn][3],
                      af[im][0], af[im][1], af[im][2], af[im][3],
                      bf[jn][0], bf[jn][1]);
    }
}

__global__ void __launch_bounds__(128, 4) qkv_gemm_kernel()
{
    extern __shared__ unsigned sm[];
    const unsigned smb32 = (unsigned)__cvta_generic_to_shared(sm);
    const int tid  = threadIdx.x;
    const int wid  = tid >> 5;
    const int lane = tid & 31;
    const int g    = lane >> 2;
    const int qd   = lane & 3;

    const int mb = blockIdx.y * 128;
    const int nb = blockIdx.x * 64;
    const int wm = (wid >> 1) * 64;
    const int wn = (wid & 1) * 32;

    const unsigned aoff = ((wm + (lane & 15)) * GSTR + (lane >> 4) * 4) * 4;
    const unsigned boff = ((wn + ((lane >> 4) << 3) + (lane & 7)) * GSTR + (((lane >> 3) & 1) << 2)) * 4;

    const unsigned* gA = g_xh + (size_t)mb * CW;
    const unsigned* gB = g_wqkvh + (size_t)nb * CW;

    float acc[4][4][4];
    #pragma unroll
    for (int i = 0; i < 4; i++)
        #pragma unroll
        for (int j = 0; j < 4; j++)
            #pragma unroll
            for (int r = 0; r < 4; r++) acc[i][j][r] = 0.f;

    gemm_prefetch(sm, sm + 2 * AW2, gA, gB, tid);
    CP_COMMIT();

    for (int kt = 0; kt < 6; ++kt) {
        CP_WAIT(0);
        __syncthreads();
        if (kt + 1 < 6) {
            int s = (kt + 1) & 1;
            gemm_prefetch(sm + s * AW2, sm + 2 * AW2 + s * BW2,
                          gA + (kt + 1) * 32, gB + (kt + 1) * 32, tid);
            CP_COMMIT();
        }
        int s = kt & 1;
        unsigned aAddr = smb32 + s * (AW2 * 4) + aoff;
        unsigned bAddr = smb32 + (2 * AW2 + s * BW2) * 4 + boff;
        gemm_compute(aAddr, bAddr, acc);
    }

    #pragma unroll
    for (int im = 0; im < 4; im++) {
        #pragma unroll
        for (int jn = 0; jn < 4; jn++) {
            int mg = mb + wm + 16 * im + g;
            int ng = nb + wn + 8 * jn + 2 * qd;
            int which = ng / CC;
            int rem   = ng - which * CC;
            int hh    = rem >> 6;
            int dw    = (rem & 63) >> 1;
            unsigned* buf = (which == 0) ? g_qh : ((which == 1) ? g_kh : g_vh);
            int b0i = mg >> 8, t0i = mg & 255;
            buf[((b0i * HH + hh) * TT + t0i) * 32 + dw] = packh2(acc[im][jn][0], acc[im][jn][1]);
            int mg2 = mg + 8;
            int b1i = mg2 >> 8, t1i = mg2 & 255;
            buf[((b1i * HH + hh) * TT + t1i) * 32 + dw] = packh2(acc[im][jn][2], acc[im][jn][3]);
        }
    }
}

__global__ void __launch_bounds__(128, 4) proj_gemm_kernel(
    const float* __restrict__ bp,
    float* __restrict__ out)
{
    extern __shared__ unsigned sm[];
    const unsigned smb32 = (unsigned)__cvta_generic_to_shared(sm);
    const int tid  = threadIdx.x;
    const int wid  = tid >> 5;
    const int lane = tid & 31;
    const int g    = lane >> 2;
    const int qd   = lane & 3;

    const int mb = blockIdx.y * 128;
    const int nb = blockIdx.x * 64;
    const int wm = (wid >> 1) * 64;
    const int wn = (wid & 1) * 32;

    const unsigned aoff = ((wm + (lane & 15)) * GSTR + (lane >> 4) * 4) * 4;
    const unsigned boff = ((wn + ((lane >> 4) << 3) + (lane & 7)) * GSTR + (((lane >> 3) & 1) << 2)) * 4;

    const unsigned* gA = g_atth + (size_t)mb * CW;
    const unsigned* gB = g_wph + (size_t)nb * CW;

    float acc[4][4][4];
    #pragma unroll
    for (int i = 0; i < 4; i++)
        #pragma unroll
        for (int j = 0; j < 4; j++)
            #pragma unroll
            for (int r = 0; r < 4; r++) acc[i][j][r] = 0.f;

    gemm_prefetch(sm, sm + 2 * AW2, gA, gB, tid);
    CP_COMMIT();

    for (int kt = 0; kt < 6; ++kt) {
        CP_WAIT(0);
        __syncthreads();
        if (kt + 1 < 6) {
            int s = (kt + 1) & 1;
            gemm_prefetch(sm + s * AW2, sm + 2 * AW2 + s * BW2,
                          gA + (kt + 1) * 32, gB + (kt + 1) * 32, tid);
            CP_COMMIT();
        }
        int s = kt & 1;
        unsigned aAddr = smb32 + s * (AW2 * 4) + aoff;
        unsigned bAddr = smb32 + (2 * AW2 + s * BW2) * 4 + boff;
        gemm_compute(aAddr, bAddr, acc);
    }

    #pragma unroll
    for (int im = 0; im < 4; im++) {
        #pragma unroll
        for (int jn = 0; jn < 4; jn++) {
            int mg = mb + wm + 16 * im + g;
            int ng = nb + wn + 8 * jn + 2 * qd;
            float b0v = bp[ng], b1v = bp[ng + 1];
            float2 v01 = make_float2(acc[im][jn][0] + b0v, acc[im][jn][1] + b1v);
            *(float2*)(out + (size_t)mg * CC + ng) = v01;
            float2 v23 = make_float2(acc[im][jn][2] + b0v, acc[im][jn][3] + b1v);
            *(float2*)(out + (size_t)(mg + 8) * CC + ng) = v23;
        }
    }
}

// ---------------------------------------------------------------------------
// Attention: 4 CTAs per (b,h); CTA q owns rows 64q..64q+63. 4 warps x 16 rows.
// f16x2 softmax: ex2.approx.f16x2 halves MUFU work and yields the packed
// fp16 P fragment directly (no packh2 in the PV section).
// ---------------------------------------------------------------------------
#define ATQ_W 2048                // Q: 64 rows x 32 words
#define AST_W 4096                // one stage: K 2048 + V 2048 words
#define ATTN_SMEM ((ATQ_W + 2*AST_W) * 4)   // 40960 bytes

__global__ void __launch_bounds__(128, 4) attn_kernel()
{
    extern __shared__ unsigned smem[];
    unsigned* Qs = smem;                     // [64][32] swizzled

    const int bh = blockIdx.x;
    const int q  = 3 - blockIdx.y;           // heavy quarters (q=3) first
    const int b  = bh / HH;
    const int h  = bh - b * HH;

    const int tid  = threadIdx.x;
    const int w    = tid >> 5;               // 0..3
    const int lane = tid & 31;
    const int g    = lane >> 2;
    const int qd   = lane & 3;

    const unsigned* qsrc = g_qh + (size_t)bh * (TT * 32) + q * 64 * 32;
    const unsigned* ksrc = g_kh + (size_t)bh * (TT * 32);
    const unsigned* vsrc = g_vh + (size_t)bh * (TT * 32);

    const unsigned smb32 = (unsigned)__cvta_generic_to_shared(smem);

    // Stage Q (64 rows x 8 chunks = 512) + KV block 0
    #pragma unroll
    for (int i = 0; i < 4; i++) {
        int lin = tid + 128 * i;             // 0..511
        int r = lin >> 3, ch = lin & 7;
        cp_async16(Qs + r * 32 + ((ch * 4) ^ swz(r & 7)), qsrc + r * 32 + ch * 4);
    }
    {
        unsigned* st = smem + ATQ_W;         // stage 0
        #pragma unroll
        for (int i = 0; i < 4; i++) {
            int lin = tid + 128 * i;         // 0..511
            int r = lin >> 3, ch = lin & 7;
            int phys = r * 32 + ((ch * 4) ^ swz(r & 7));
            cp_async16(st + phys,        ksrc + r * 32 + ch * 4);
            cp_async16(st + 2048 + phys, vsrc + r * 32 + ch * 4);
        }
    }
    CP_COMMIT();

    const int wminrow = 64 * q + 16 * w;

    float o[8][4];
    #pragma unroll
    for (int j = 0; j < 8; j++)
        #pragma unroll
        for (int r = 0; r < 4; r++) o[j][r] = 0.f;
    float row_max[2] = {-1e30f, -1e30f};
    float row_sum[2] = {0.f, 0.f};

    const int r0 = 16 * w + g;               // local Q row
    const int sg = swz(g);

    const int lmat = lane >> 3;              // 0..3
    const int lr8  = lane & 7;
    const int vrow_off = ((lmat & 1) << 3) + lr8;    // + 16*ks
    const int vswz = swz(lr8);

    for (int jb = 0; jb <= q; ++jb) {
        CP_WAIT(0);
        __syncthreads();
        if (jb < q) {
            unsigned* st = smem + ATQ_W + ((jb + 1) & 1) * AST_W;
            const unsigned* kg = ksrc + (jb + 1) * 64 * 32;
            const unsigned* vg = vsrc + (jb + 1) * 64 * 32;
            #pragma unroll
            for (int i = 0; i < 4; i++) {
                int lin = tid + 128 * i;
                int r = lin >> 3, ch = lin & 7;
                int phys = r * 32 + ((ch * 4) ^ swz(r & 7));
                cp_async16(st + phys,        kg + r * 32 + ch * 4);
                cp_async16(st + 2048 + phys, vg + r * 32 + ch * 4);
            }
            CP_COMMIT();
        }

        const unsigned* K = smem + ATQ_W + (jb & 1) * AST_W;
        const unsigned vb32 = smb32 + (ATQ_W + (jb & 1) * AST_W + 2048) * 4;

        // ---- S = Q K^T  (4 ksteps of k16) ----
        float s[8][4];
        #pragma unroll
        for (int j = 0; j < 8; j++)
            #pragma unroll
            for (int r = 0; r < 4; r++) s[j][r] = 0.f;

        #pragma unroll
        for (int ks = 0; ks < 4; ++ks) {
            const int cs = (8 * ks + qd) ^ sg;
            unsigned a0 = Qs[r0 * 32 + cs];
            unsigned a1 = Qs[(r0 + 8) * 32 + cs];
            unsigned a2 = Qs[r0 * 32 + (cs ^ 4)];
            unsigned a3 = Qs[(r0 + 8) * 32 + (cs ^ 4)];
            #pragma unroll
            for (int jn = 0; jn < 8; jn++) {
                unsigned b0 = K[(8 * jn + g) * 32 + cs];
                unsigned b1 = K[(8 * jn + g) * 32 + (cs ^ 4)];
                mma16(s[jn][0], s[jn][1], s[jn][2], s[jn][3],
                      a0, a1, a2, a3, b0, b1);
            }
        }

        // ---- causal mask (only the diagonal block jb == q) ----
        if (jb == q) {
            #pragma unroll
            for (int hf = 0; hf < 2; hf++) {
                int trow = wminrow + 8 * hf + g;
                #pragma unroll
                for (int jn = 0; jn < 8; jn++) {
                    #pragma unroll
                    for (int e = 0; e < 2; e++) {
                        int col = jb * 64 + 8 * jn + 2 * qd + e;
                        if (col > trow) s[jn][2 * hf + e] = -1e30f;
                    }
                }
            }
        }

        // ---- online softmax (base-2 domain, f16x2 exp) ----
        unsigned ps[8][2];                   // packed P fragments [jn][hf]
        #pragma unroll
        for (int hf = 0; hf < 2; hf++) {
            float rmax = -1e30f;
            #pragma unroll
            for (int jn = 0; jn < 8; jn++)
                rmax = fmaxf(rmax, fmaxf(s[jn][2 * hf], s[jn][2 * hf + 1]));
            rmax = fmaxf(rmax, __shfl_xor_sync(0xffffffffu, rmax, 1));
            rmax = fmaxf(rmax, __shfl_xor_sync(0xffffffffu, rmax, 2));
            float mnew = fmaxf(row_max[hf], rmax);
            float corr = ex2f(row_max[hf] - mnew);
            row_max[hf] = mnew;
            float psum = 0.f;
            #pragma unroll
            for (int jn = 0; jn < 8; jn++) {
                unsigned pp = packh2(s[jn][2 * hf] - mnew, s[jn][2 * hf + 1] - mnew);
                pp = ex2h2(pp);
                ps[jn][hf] = pp;
                float2 pf = h22f2(pp);
                psum += pf.x + pf.y;
            }
            psum += __shfl_xor_sync(0xffffffffu, psum, 1);
            psum += __shfl_xor_sync(0xffffffffu, psum, 2);
            row_sum[hf] = row_sum[hf] * corr + psum;
            #pragma unroll
            for (int jn = 0; jn < 8; jn++) {
                o[jn][2 * hf + 0] *= corr;
                o[jn][2 * hf + 1] *= corr;
            }
        }

        // ---- O += P V  (P fragments already packed by ex2h2) ----
        #pragma unroll
        for (int ks = 0; ks < 4; ++ks) {
            unsigned pa0 = ps[2 * ks][0];
            unsigned pa1 = ps[2 * ks][1];
            unsigned pa2 = ps[2 * ks + 1][0];
            unsigned pa3 = ps[2 * ks + 1][1];

            unsigned vb[4][4];
            #pragma unroll
            for (int jnp = 0; jnp < 4; jnp++) {
                int vrow = 16 * ks + vrow_off;
                int wc = (4 * (2 * jnp + (lmat >> 1))) ^ vswz;
                unsigned addr = vb32 + (vrow * 32 + wc) * 4;
                asm volatile(
                    "ldmatrix.sync.aligned.m8n8.x4.trans.shared.b16 {%0,%1,%2,%3}, [%4];"
                    : "=r"(vb[jnp][0]), "=r"(vb[jnp][1]), "=r"(vb[jnp][2]), "=r"(vb[jnp][3])
                    : "r"(addr));
            }
            #pragma unroll
            for (int jn = 0; jn < 8; jn++) {
                unsigned b0 = vb[jn >> 1][(jn & 1) * 2];
                unsigned b1 = vb[jn >> 1][(jn & 1) * 2 + 1];
                mma16(o[jn][0], o[jn][1], o[jn][2], o[jn][3],
                      pa0, pa1, pa2, pa3, b0, b1);
            }
        }
    }

    // ---- normalize + store fp16 to g_atth [B][T][384] ----
    float inv0 = 1.0f / row_sum[0];
    float inv1 = 1.0f / row_sum[1];
    int trow = 64 * q + 16 * w + g;
    #pragma unroll
    for (int jn = 0; jn < 8; jn++) {
        int wdd = h * 32 + 4 * jn + qd;
        g_atth[(size_t)(b * TT + trow) * CW + wdd]       = packh2(o[jn][0] * inv0, o[jn][1] * inv0);
        g_atth[(size_t)(b * TT + trow + 8) * CW + wdd]   = packh2(o[jn][2] * inv1, o[jn][3] * inv1);
    }
}

// ---------------------------------------------------------------------------
extern "C" void kernel_launch(void* const* d_in, const int* in_sizes, int n_in,
                              void* d_out, int out_size)
{
    const float* x  = (const float*)d_in[0];
    const float* Wq = (const float*)d_in[1];
    const float* Wk = (const float*)d_in[2];
    const float* Wv = (const float*)d_in[3];
    const float* Wp = (const float*)d_in[4];
    const float* bp = (const float*)d_in[5];
    float* out = (float*)d_out;

    static bool attr_set = false;
    if (!attr_set) {
        cudaFuncSetAttribute(qkv_gemm_kernel,  cudaFuncAttributeMaxDynamicSharedMemorySize, GEMM_SMEM);
        cudaFuncSetAttribute(proj_gemm_kernel, cudaFuncAttributeMaxDynamicSharedMemorySize, GEMM_SMEM);
        cudaFuncSetAttribute(attn_kernel,      cudaFuncAttributeMaxDynamicSharedMemorySize, ATTN_SMEM);
        attr_set = true;
    }

    prep_kernel<<<NCONV + NPACK, 256>>>(x, Wq, Wk, Wv, Wp);
    qkv_gemm_kernel<<<dim3(18, 256), 128, GEMM_SMEM>>>();
    attn_kernel<<<dim3(BB * HH, 4), 128, ATTN_SMEM>>>();
    proj_gemm_kernel<<<dim3(6, 256), 128, GEMM_SMEM>>>(bp, out);
}

// round 17
// speedup vs baseline: 1.0646x; 1.0079x over previous
#include <cuda_runtime.h>
#include <cuda_fp16.h>
#include <cstdint>

// Problem sizes
#define BB   128
#define TT   256
#define CC   384
#define HH   6
#define HSZ  64
#define MTOT (BB*TT)          // 32768
#define NQKV 1152
#define CW   192              // CC/2 half2-words per row

// Scratch: fp16 data stored as half2 packed in unsigned words
__device__ __align__(16) unsigned g_xh[MTOT*CW];        // x fp16
__device__ __align__(16) unsigned g_wqkvh[NQKV*CW];     // B[n][k] fp16, Wq pre-scaled
__device__ __align__(16) unsigned g_wph[CC*CW];         // Wp[n][k] fp16
__device__ __align__(16) unsigned g_qh[BB*HH*TT*32];    // [B][H][T][64] fp16 (pre-scaled)
__device__ __align__(16) unsigned g_kh[BB*HH*TT*32];
__device__ __align__(16) unsigned g_vh[BB*HH*TT*32];
__device__ __align__(16) unsigned g_atth[MTOT*CW];      // [B][T][384] fp16

#define QSCALE 0.1803368801111204f   // 0.125 * log2(e)

// PDL primitives
#define GDC_WAIT()   asm volatile("griddepcontrol.wait;" ::: "memory")
#define GDC_LAUNCH() asm volatile("griddepcontrol.launch_dependents;" ::: "memory")

__device__ __forceinline__ unsigned packh2(float lo, float hi) {
    unsigned u;
    asm("cvt.rn.f16x2.f32 %0, %1, %2;" : "=r"(u) : "f"(hi), "f"(lo));
    return u;
}

__device__ __forceinline__ float ex2f(float x) {
    float y;
    asm("ex2.approx.f32 %0, %1;" : "=f"(y) : "f"(x));
    return y;
}

__device__ __forceinline__ unsigned ex2h2(unsigned a) {
    unsigned d;
    asm("ex2.approx.f16x2 %0, %1;" : "=r"(d) : "r"(a));
    return d;
}

__device__ __forceinline__ float2 h22f2(unsigned a) {
    float lo, hi;
    asm("{\n\t.reg .f16 l, h;\n\tmov.b32 {l, h}, %2;\n\t"
        "cvt.f32.f16 %0, l;\n\tcvt.f32.f16 %1, h;\n\t}"
        : "=f"(lo), "=f"(hi) : "r"(a));
    return make_float2(lo, hi);
}

__device__ __forceinline__ void cp_async16(unsigned* smem_dst, const unsigned* gsrc) {
    unsigned s = (unsigned)__cvta_generic_to_shared(smem_dst);
    asm volatile("cp.async.cg.shared.global [%0], [%1], 16;\n" :: "r"(s), "l"(gsrc));
}
#define CP_COMMIT() asm volatile("cp.async.commit_group;\n" ::: "memory")
#define CP_WAIT(N)  asm volatile("cp.async.wait_group %0;\n" :: "n"(N) : "memory")

// fp16 mma m16n8k16, fp32 accumulate
__device__ __forceinline__ void mma16(float& c0, float& c1, float& c2, float& c3,
                                      unsigned a0, unsigned a1, unsigned a2, unsigned a3,
                                      unsigned b0, unsigned b1) {
    asm volatile(
        "mma.sync.aligned.m16n8k16.row.col.f32.f16.f16.f32 "
        "{%0,%1,%2,%3}, {%4,%5,%6,%7}, {%8,%9}, {%0,%1,%2,%3};\n"
        : "+f"(c0), "+f"(c1), "+f"(c2), "+f"(c3)
        : "r"(a0), "r"(a1), "r"(a2), "r"(a3), "r"(b0), "r"(b1));
}

__device__ __forceinline__ void ldsm_x4(unsigned& r0, unsigned& r1, unsigned& r2, unsigned& r3,
                                        unsigned addr) {
    asm volatile("ldmatrix.sync.aligned.m8n8.x4.shared.b16 {%0,%1,%2,%3}, [%4];"
                 : "=r"(r0), "=r"(r1), "=r"(r2), "=r"(r3) : "r"(addr));
}

// bit-reverse-3 XOR swizzle on word index (16B granularity, bits 2-4)
__device__ __forceinline__ int swz(int r) {
    return ((r & 1) << 4) | ((r & 2) << 2) | (r & 4);
}

// ---------------------------------------------------------------------------
// Merged prep kernel
// ---------------------------------------------------------------------------
#define NCONV (MTOT * CC / (256 * 8))      // 6144
#define NPACK ((NQKV * CW + 255) / 256)    // 864

__global__ void __launch_bounds__(256) prep_kernel(
    const float* __restrict__ x,
    const float* __restrict__ Wq, const float* __restrict__ Wk,
    const float* __restrict__ Wv, const float* __restrict__ Wp)
{
    if (blockIdx.x < NCONV) {
        int i = (blockIdx.x * 256 + threadIdx.x) * 8;
        float4 v0 = *(const float4*)(x + i);
        float4 v1 = *(const float4*)(x + i + 4);
        uint4 o;
        o.x = packh2(v0.x, v0.y);
        o.y = packh2(v0.z, v0.w);
        o.z = packh2(v1.x, v1.y);
        o.w = packh2(v1.z, v1.w);
        *(uint4*)(g_xh + i / 2) = o;
        GDC_LAUNCH();
        return;
    }
    int wi = (blockIdx.x - NCONV) * 256 + threadIdx.x;   // word index
    if (wi < NQKV * CW) {
        int n = wi / CW, kw = wi - (wi / CW) * CW;
        int which = n / CC;
        int rem = n - which * CC;
        int h = rem >> 6, d = rem & 63;
        const float* W = (which == 0) ? Wq : ((which == 1) ? Wk : Wv);
        float v0 = W[h * (CC * HSZ) + (2 * kw) * HSZ + d];
        float v1 = W[h * (CC * HSZ) + (2 * kw + 1) * HSZ + d];
        if (which == 0) { v0 *= QSCALE; v1 *= QSCALE; }
        g_wqkvh[wi] = packh2(v0, v1);
    }
    if (wi < CC * CW) {
        int n = wi / CW, kw = wi - (wi / CW) * CW;
        g_wph[wi] = packh2(Wp[n * CC + 2 * kw], Wp[n * CC + 2 * kw + 1]);
    }
    GDC_LAUNCH();
}

// ---------------------------------------------------------------------------
// fp16 GEMM (R13 winner): CTA 128x64, 128 threads (4 warps of 64x32),
// BK=64 halves, 2-stage cp.async, one barrier per kt, 4 CTAs/SM.
// ---------------------------------------------------------------------------
#define GSTR 36
#define AW2 (128*GSTR)    // 4608 words per A stage
#define BW2 (64*GSTR)     // 2304 words per B stage
#define GEMM_SMEM ((2*AW2 + 2*BW2) * 4)   // 55296 B

__device__ __forceinline__ void gemm_prefetch(unsigned* smA, unsigned* smB,
                                              const unsigned* gA, const unsigned* gB,
                                              int tid) {
    #pragma unroll
    for (int it = 0; it < 8; ++it) {
        int idx = tid + it * 128;       // 0..1023: A 128 rows x 8 chunks
        int row = idx >> 3, ch = idx & 7;
        cp_async16(smA + row * GSTR + ch * 4, gA + (size_t)row * CW + ch * 4);
    }
    #pragma unroll
    for (int it = 0; it < 4; ++it) {
        int idx = tid + it * 128;       // 0..511: B 64 rows x 8 chunks
        int row = idx >> 3, ch = idx & 7;
        cp_async16(smB + row * GSTR + ch * 4, gB + (size_t)row * CW + ch * 4);
    }
}

__device__ __forceinline__ void gemm_compute(unsigned aAddr, unsigned bAddr,
                                             float acc[4][4][4]) {
    #pragma unroll
    for (int ks = 0; ks < 4; ++ks) {
        unsigned af[4][4];
        unsigned bf[4][2];
        #pragma unroll
        for (int im = 0; im < 4; im++)
            ldsm_x4(af[im][0], af[im][1], af[im][2], af[im][3],
                    aAddr + im * (16 * GSTR * 4) + ks * 32);
        #pragma unroll
        for (int jnp = 0; jnp < 2; jnp++)
            ldsm_x4(bf[2 * jnp][0], bf[2 * jnp][1], bf[2 * jnp + 1][0], bf[2 * jnp + 1][1],
                    bAddr + jnp * (16 * GSTR * 4) + ks * 32);
        #pragma unroll
        for (int im = 0; im < 4; im++)
            #pragma unroll
            for (int jn = 0; jn < 4; jn++)
                mma16(acc[im][jn][0], acc[im][jn][1], acc[im][jn][2], acc[im][jn][3],
                      af[im][0], af[im][1], af[im][2], af[im][3],
                      bf[jn][0], bf[jn][1]);
    }
}

__global__ void __launch_bounds__(128, 4) qkv_gemm_kernel()
{
    extern __shared__ unsigned sm[];
    const unsigned smb32 = (unsigned)__cvta_generic_to_shared(sm);
    const int tid  = threadIdx.x;
    const int wid  = tid >> 5;
    const int lane = tid & 31;
    const int g    = lane >> 2;
    const int qd   = lane & 3;

    const int mb = blockIdx.y * 128;
    const int nb = blockIdx.x * 64;
    const int wm = (wid >> 1) * 64;
    const int wn = (wid & 1) * 32;

    const unsigned aoff = ((wm + (lane & 15)) * GSTR + (lane >> 4) * 4) * 4;
    const unsigned boff = ((wn + ((lane >> 4) << 3) + (lane & 7)) * GSTR + (((lane >> 3) & 1) << 2)) * 4;

    const unsigned* gA = g_xh + (size_t)mb * CW;
    const unsigned* gB = g_wqkvh + (size_t)nb * CW;

    float acc[4][4][4];
    #pragma unroll
    for (int i = 0; i < 4; i++)
        #pragma unroll
        for (int j = 0; j < 4; j++)
            #pragma unroll
            for (int r = 0; r < 4; r++) acc[i][j][r] = 0.f;

    GDC_WAIT();                 // prep outputs must be visible
    gemm_prefetch(sm, sm + 2 * AW2, gA, gB, tid);
    CP_COMMIT();

    for (int kt = 0; kt < 6; ++kt) {
        CP_WAIT(0);
        __syncthreads();
        if (kt + 1 < 6) {
            int s = (kt + 1) & 1;
            gemm_prefetch(sm + s * AW2, sm + 2 * AW2 + s * BW2,
                          gA + (kt + 1) * 32, gB + (kt + 1) * 32, tid);
            CP_COMMIT();
        }
        int s = kt & 1;
        unsigned aAddr = smb32 + s * (AW2 * 4) + aoff;
        unsigned bAddr = smb32 + (2 * AW2 + s * BW2) * 4 + boff;
        gemm_compute(aAddr, bAddr, acc);
    }

    #pragma unroll
    for (int im = 0; im < 4; im++) {
        #pragma unroll
        for (int jn = 0; jn < 4; jn++) {
            int mg = mb + wm + 16 * im + g;
            int ng = nb + wn + 8 * jn + 2 * qd;
            int which = ng / CC;
            int rem   = ng - which * CC;
            int hh    = rem >> 6;
            int dw    = (rem & 63) >> 1;
            unsigned* buf = (which == 0) ? g_qh : ((which == 1) ? g_kh : g_vh);
            int b0i = mg >> 8, t0i = mg & 255;
            buf[((b0i * HH + hh) * TT + t0i) * 32 + dw] = packh2(acc[im][jn][0], acc[im][jn][1]);
            int mg2 = mg + 8;
            int b1i = mg2 >> 8, t1i = mg2 & 255;
            buf[((b1i * HH + hh) * TT + t1i) * 32 + dw] = packh2(acc[im][jn][2], acc[im][jn][3]);
        }
    }
    GDC_LAUNCH();
}

__global__ void __launch_bounds__(128, 4) proj_gemm_kernel(
    const float* __restrict__ bp,
    float* __restrict__ out)
{
    extern __shared__ unsigned sm[];
    const unsigned smb32 = (unsigned)__cvta_generic_to_shared(sm);
    const int tid  = threadIdx.x;
    const int wid  = tid >> 5;
    const int lane = tid & 31;
    const int g    = lane >> 2;
    const int qd   = lane & 3;

    const int mb = blockIdx.y * 128;
    const int nb = blockIdx.x * 64;
    const int wm = (wid >> 1) * 64;
    const int wn = (wid & 1) * 32;

    const unsigned aoff = ((wm + (lane & 15)) * GSTR + (lane >> 4) * 4) * 4;
    const unsigned boff = ((wn + ((lane >> 4) << 3) + (lane & 7)) * GSTR + (((lane >> 3) & 1) << 2)) * 4;

    const unsigned* gA = g_atth + (size_t)mb * CW;
    const unsigned* gB = g_wph + (size_t)nb * CW;

    float acc[4][4][4];
    #pragma unroll
    for (int i = 0; i < 4; i++)
        #pragma unroll
        for (int j = 0; j < 4; j++)
            #pragma unroll
            for (int r = 0; r < 4; r++) acc[i][j][r] = 0.f;

    GDC_WAIT();                 // attn outputs must be visible
    gemm_prefetch(sm, sm + 2 * AW2, gA, gB, tid);
    CP_COMMIT();

    for (int kt = 0; kt < 6; ++kt) {
        CP_WAIT(0);
        __syncthreads();
        if (kt + 1 < 6) {
            int s = (kt + 1) & 1;
            gemm_prefetch(sm + s * AW2, sm + 2 * AW2 + s * BW2,
                          gA + (kt + 1) * 32, gB + (kt + 1) * 32, tid);
            CP_COMMIT();
        }
        int s = kt & 1;
        unsigned aAddr = smb32 + s * (AW2 * 4) + aoff;
        unsigned bAddr = smb32 + (2 * AW2 + s * BW2) * 4 + boff;
        gemm_compute(aAddr, bAddr, acc);
    }

    #pragma unroll
    for (int im = 0; im < 4; im++) {
        #pragma unroll
        for (int jn = 0; jn < 4; jn++) {
            int mg = mb + wm + 16 * im + g;
            int ng = nb + wn + 8 * jn + 2 * qd;
            float b0v = bp[ng], b1v = bp[ng + 1];
            float2 v01 = make_float2(acc[im][jn][0] + b0v, acc[im][jn][1] + b1v);
            *(float2*)(out + (size_t)mg * CC + ng) = v01;
            float2 v23 = make_float2(acc[im][jn][2] + b0v, acc[im][jn][3] + b1v);
            *(float2*)(out + (size_t)(mg + 8) * CC + ng) = v23;
        }
    }
}

// ---------------------------------------------------------------------------
// Attention: 4 CTAs per (b,h); CTA q owns rows 64q..64q+63. 4 warps x 16 rows.
// f16x2 softmax; packed P fragments feed PV directly.
// ---------------------------------------------------------------------------
#define ATQ_W 2048                // Q: 64 rows x 32 words
#define AST_W 4096                // one stage: K 2048 + V 2048 words
#define ATTN_SMEM ((ATQ_W + 2*AST_W) * 4)   // 40960 bytes

__global__ void __launch_bounds__(128, 4) attn_kernel()
{
    extern __shared__ unsigned smem[];
    unsigned* Qs = smem;                     // [64][32] swizzled

    const int bh = blockIdx.x;
    const int q  = 3 - blockIdx.y;           // heavy quarters (q=3) first
    const int b  = bh / HH;
    const int h  = bh - b * HH;

    const int tid  = threadIdx.x;
    const int w    = tid >> 5;               // 0..3
    const int lane = tid & 31;
    const int g    = lane >> 2;
    const int qd   = lane & 3;

    const unsigned* qsrc = g_qh + (size_t)bh * (TT * 32) + q * 64 * 32;
    const unsigned* ksrc = g_kh + (size_t)bh * (TT * 32);
    const unsigned* vsrc = g_vh + (size_t)bh * (TT * 32);

    const unsigned smb32 = (unsigned)__cvta_generic_to_shared(smem);

    GDC_WAIT();                 // qkv outputs must be visible

    // Stage Q (64 rows x 8 chunks = 512) + KV block 0
    #pragma unroll
    for (int i = 0; i < 4; i++) {
        int lin = tid + 128 * i;             // 0..511
        int r = lin >> 3, ch = lin & 7;
        cp_async16(Qs + r * 32 + ((ch * 4) ^ swz(r & 7)), qsrc + r * 32 + ch * 4);
    }
    {
        unsigned* st = smem + ATQ_W;         // stage 0
        #pragma unroll
        for (int i = 0; i < 4; i++) {
            int lin = tid + 128 * i;         // 0..511
            int r = lin >> 3, ch = lin & 7;
            int phys = r * 32 + ((ch * 4) ^ swz(r & 7));
            cp_async16(st + phys,        ksrc + r * 32 + ch * 4);
            cp_async16(st + 2048 + phys, vsrc + r * 32 + ch * 4);
        }
    }
    CP_COMMIT();

    const int wminrow = 64 * q + 16 * w;

    float o[8][4];
    #pragma unroll
    for (int j = 0; j < 8; j++)
        #pragma unroll
        for (int r = 0; r < 4; r++) o[j][r] = 0.f;
    float row_max[2] = {-1e30f, -1e30f};
    float row_sum[2] = {0.f, 0.f};

    const int r0 = 16 * w + g;               // local Q row
    const int sg = swz(g);

    const int lmat = lane >> 3;              // 0..3
    const int lr8  = lane & 7;
    const int vrow_off = ((lmat & 1) << 3) + lr8;    // + 16*ks
    const int vswz = swz(lr8);

    for (int jb = 0; jb <= q; ++jb) {
        CP_WAIT(0);
        __syncthreads();
        if (jb < q) {
            unsigned* st = smem + ATQ_W + ((jb + 1) & 1) * AST_W;
            const unsigned* kg = ksrc + (jb + 1) * 64 * 32;
            const unsigned* vg = vsrc + (jb + 1) * 64 * 32;
            #pragma unroll
            for (int i = 0; i < 4; i++) {
                int lin = tid + 128 * i;
                int r = lin >> 3, ch = lin & 7;
                int phys = r * 32 + ((ch * 4) ^ swz(r & 7));
                cp_async16(st + phys,        kg + r * 32 + ch * 4);
                cp_async16(st + 2048 + phys, vg + r * 32 + ch * 4);
            }
            CP_COMMIT();
        }

        const unsigned* K = smem + ATQ_W + (jb & 1) * AST_W;
        const unsigned vb32 = smb32 + (ATQ_W + (jb & 1) * AST_W + 2048) * 4;

        // ---- S = Q K^T  (4 ksteps of k16) ----
        float s[8][4];
        #pragma unroll
        for (int j = 0; j < 8; j++)
            #pragma unroll
            for (int r = 0; r < 4; r++) s[j][r] = 0.f;

        #pragma unroll
        for (int ks = 0; ks < 4; ++ks) {
            const int cs = (8 * ks + qd) ^ sg;
            unsigned a0 = Qs[r0 * 32 + cs];
            unsigned a1 = Qs[(r0 + 8) * 32 + cs];
            unsigned a2 = Qs[r0 * 32 + (cs ^ 4)];
            unsigned a3 = Qs[(r0 + 8) * 32 + (cs ^ 4)];
            #pragma unroll
            for (int jn = 0; jn < 8; jn++) {
                unsigned b0 = K[(8 * jn + g) * 32 + cs];
                unsigned b1 = K[(8 * jn + g) * 32 + (cs ^ 4)];
                mma16(s[jn][0], s[jn][1], s[jn][2], s[jn][3],
                      a0, a1, a2, a3, b0, b1);
            }
        }

        // ---- causal mask (only the diagonal block jb == q) ----
        if (jb == q) {
            #pragma unroll
            for (int hf = 0; hf < 2; hf++) {
                int trow = wminrow + 8 * hf + g;
                #pragma unroll
                for (int jn = 0; jn < 8; jn++) {
                    #pragma unroll
                    for (int e = 0; e < 2; e++) {
                        int col = jb * 64 + 8 * jn + 2 * qd + e;
                        if (col > trow) s[jn][2 * hf + e] = -1e30f;
                    }
                }
            }
        }

        // ---- online softmax (base-2 domain, f16x2 exp) ----
        unsigned ps[8][2];                   // packed P fragments [jn][hf]
        #pragma unroll
        for (int hf = 0; hf < 2; hf++) {
            float rmax = -1e30f;
            #pragma unroll
            for (int jn = 0; jn < 8; jn++)
                rmax = fmaxf(rmax, fmaxf(s[jn][2 * hf], s[jn][2 * hf + 1]));
            rmax = fmaxf(rmax, __shfl_xor_sync(0xffffffffu, rmax, 1));
            rmax = fmaxf(rmax, __shfl_xor_sync(0xffffffffu, rmax, 2));
            float mnew = fmaxf(row_max[hf], rmax);
            float corr = ex2f(row_max[hf] - mnew);
            row_max[hf] = mnew;
            float psum = 0.f;
            #pragma unroll
            for (int jn = 0; jn < 8; jn++) {
                unsigned pp = packh2(s[jn][2 * hf] - mnew, s[jn][2 * hf + 1] - mnew);
                pp = ex2h2(pp);
                ps[jn][hf] = pp;
                float2 pf = h22f2(pp);
                psum += pf.x + pf.y;
            }
            psum += __shfl_xor_sync(0xffffffffu, psum, 1);
            psum += __shfl_xor_sync(0xffffffffu, psum, 2);
            row_sum[hf] = row_sum[hf] * corr + psum;
            #pragma unroll
            for (int jn = 0; jn < 8; jn++) {
                o[jn][2 * hf + 0] *= corr;
                o[jn][2 * hf + 1] *= corr;
            }
        }

        // ---- O += P V  (P fragments already packed by ex2h2) ----
        #pragma unroll
        for (int ks = 0; ks < 4; ++ks) {
            unsigned pa0 = ps[2 * ks][0];
            unsigned pa1 = ps[2 * ks][1];
            unsigned pa2 = ps[2 * ks + 1][0];
            unsigned pa3 = ps[2 * ks + 1][1];

            unsigned vb[4][4];
            #pragma unroll
            for (int jnp = 0; jnp < 4; jnp++) {
                int vrow = 16 * ks + vrow_off;
                int wc = (4 * (2 * jnp + (lmat >> 1))) ^ vswz;
                unsigned addr = vb32 + (vrow * 32 + wc) * 4;
                asm volatile(
                    "ldmatrix.sync.aligned.m8n8.x4.trans.shared.b16 {%0,%1,%2,%3}, [%4];"
                    : "=r"(vb[jnp][0]), "=r"(vb[jnp][1]), "=r"(vb[jnp][2]), "=r"(vb[jnp][3])
                    : "r"(addr));
            }
            #pragma unroll
            for (int jn = 0; jn < 8; jn++) {
                unsigned b0 = vb[jn >> 1][(jn & 1) * 2];
                unsigned b1 = vb[jn >> 1][(jn & 1) * 2 + 1];
                mma16(o[jn][0], o[jn][1], o[jn][2], o[jn][3],
                      pa0, pa1, pa2, pa3, b0, b1);
            }
        }
    }

    // ---- normalize + store fp16 to g_atth [B][T][384] ----
    float inv0 = 1.0f / row_sum[0];
    float inv1 = 1.0f / row_sum[1];
    int trow = 64 * q + 16 * w + g;
    #pragma unroll
    for (int jn = 0; jn < 8; jn++) {
        int wdd = h * 32 + 4 * jn + qd;
        g_atth[(size_t)(b * TT + trow) * CW + wdd]       = packh2(o[jn][0] * inv0, o[jn][1] * inv0);
        g_atth[(size_t)(b * TT + trow + 8) * CW + wdd]   = packh2(o[jn][2] * inv1, o[jn][3] * inv1);
    }
    GDC_LAUNCH();
}

// ---------------------------------------------------------------------------
extern "C" void kernel_launch(void* const* d_in, const int* in_sizes, int n_in,
                              void* d_out, int out_size)
{
    const float* x  = (const float*)d_in[0];
    const float* Wq = (const float*)d_in[1];
    const float* Wk = (const float*)d_in[2];
    const float* Wv = (const float*)d_in[3];
    const float* Wp = (const float*)d_in[4];
    const float* bp = (const float*)d_in[5];
    float* out = (float*)d_out;

    static bool attr_set = false;
    if (!attr_set) {
        cudaFuncSetAttribute(qkv_gemm_kernel,  cudaFuncAttributeMaxDynamicSharedMemorySize, GEMM_SMEM);
        cudaFuncSetAttribute(proj_gemm_kernel, cudaFuncAttributeMaxDynamicSharedMemorySize, GEMM_SMEM);
        cudaFuncSetAttribute(attn_kernel,      cudaFuncAttributeMaxDynamicSharedMemorySize, ATTN_SMEM);
        attr_set = true;
    }

    prep_kernel<<<NCONV + NPACK, 256>>>(x, Wq, Wk, Wv, Wp);

    cudaLaunchAttribute pdl[1];
    pdl[0].id = cudaLaunchAttributeProgrammaticStreamSerialization;
    pdl[0].val.programmaticStreamSerializationAllowed = 1;

    {
        cudaLaunchConfig_t cfg = {};
        cfg.gridDim = dim3(18, 256);
        cfg.blockDim = dim3(128);
        cfg.dynamicSmemBytes = GEMM_SMEM;
        cfg.attrs = pdl;
        cfg.numAttrs = 1;
        cudaLaunchKernelEx(&cfg, qkv_gemm_kernel);
    }
    {
        cudaLaunchConfig_t cfg = {};
        cfg.gridDim = dim3(BB * HH, 4);
        cfg.blockDim = dim3(128);
        cfg.dynamicSmemBytes = ATTN_SMEM;
        cfg.attrs = pdl;
        cfg.numAttrs = 1;
        cudaLaunchKernelEx(&cfg, attn_kernel);
    }
    {
        cudaLaunchConfig_t cfg = {};
        cfg.gridDim = dim3(6, 256);
        cfg.blockDim = dim3(128);
        cfg.dynamicSmemBytes = GEMM_SMEM;
        cfg.attrs = pdl;
        cfg.numAttrs = 1;
        cudaLaunchKernelEx(&cfg, proj_gemm_kernel, bp, out);
    }
}